// round 10
// baseline (speedup 1.0000x reference)
#include <cuda_runtime.h>
#include <math.h>

#define MSIZE 8192
// a = q / sqrt(1024) ; fold log2(e) so exp(x) = ex2(x * log2e)
#define A_SCALE (1.44269504088896340736f / 32.0f)

// Scratch (no allocation allowed): k, v vectors. q stays in registers.
__device__ float g_k[MSIZE];
__device__ float g_v[MSIZE];

__device__ __forceinline__ float ex2f(float x) {
    float y;
    asm("ex2.approx.f32 %0, %1;" : "=f"(y) : "f"(x));
    return y;
}

// ---------------------------------------------------------------------------
// Kernel 1: K and V GEMV.  One warp per TWO output rows; 8 warps per block.
// grid.x = (2*MSIZE/2)/8 = 1024.  x staged in smem (32 KB).
// W streamed with .cs (evict-first); zero reuse.
// ---------------------------------------------------------------------------
__global__ __launch_bounds__(256) void kv_gemv(
    const float* __restrict__ x,
    const float* __restrict__ Wk, const float* __restrict__ bk,
    const float* __restrict__ Wv, const float* __restrict__ bv)
{
    __shared__ float sx[MSIZE];
    for (int i = threadIdx.x; i < MSIZE / 4; i += blockDim.x)
        ((float4*)sx)[i] = ((const float4*)x)[i];
    __syncthreads();

    const int warp = threadIdx.x >> 5;
    const int lane = threadIdx.x & 31;
    const int pair = blockIdx.x * 8 + warp;      // 0 .. 8191 (2 rows each)
    const int mat  = pair >> 12;                 // 0 = K, 1 = V
    const int row  = (pair & 4095) * 2;

    const float* W = (mat == 0) ? Wk : Wv;
    const float* b = (mat == 0) ? bk : bv;
    float*       o = (mat == 0) ? g_k : g_v;

    const float4* __restrict__ W0 = (const float4*)(W + (size_t)row * MSIZE);
    const float4* __restrict__ W1 = (const float4*)(W + (size_t)(row + 1) * MSIZE);
    const float4* __restrict__ xv = (const float4*)sx;

    float acc0 = 0.0f, acc1 = 0.0f;
#pragma unroll 8
    for (int i = lane; i < MSIZE / 4; i += 32) {
        float4 w0 = __ldcs(W0 + i);
        float4 w1 = __ldcs(W1 + i);
        float4 xx = xv[i];
        acc0 = fmaf(w0.x, xx.x, acc0);
        acc0 = fmaf(w0.y, xx.y, acc0);
        acc0 = fmaf(w0.z, xx.z, acc0);
        acc0 = fmaf(w0.w, xx.w, acc0);
        acc1 = fmaf(w1.x, xx.x, acc1);
        acc1 = fmaf(w1.y, xx.y, acc1);
        acc1 = fmaf(w1.z, xx.z, acc1);
        acc1 = fmaf(w1.w, xx.w, acc1);
    }
#pragma unroll
    for (int off = 16; off > 0; off >>= 1) {
        acc0 += __shfl_xor_sync(0xffffffffu, acc0, off);
        acc1 += __shfl_xor_sync(0xffffffffu, acc1, off);
    }

    if (lane == 0) {
        o[row]     = acc0 + b[row];
        o[row + 1] = acc1 + b[row + 1];
    }
}

// ---------------------------------------------------------------------------
// Kernel 2: FUSED Q-GEMV + rank-1 softmax attention.
// Each warp: (a) computes q[row], q[row+1] via gemv (DRAM-bound, .cs streams),
//            (b) immediately runs attention for those two rows (MUFU-bound).
// q never leaves registers.  Overlap across co-resident CTAs hides the MUFU
// phase inside the DRAM phase of other warps/CTAs.
// No smem: full 228 KB L1 keeps x (32 KB) + k,v (64 KB) resident.
// 128 threads = 4 warps, 8 rows/CTA, grid = 1024.
// ---------------------------------------------------------------------------
__global__ __launch_bounds__(128) void q_attn(
    const float* __restrict__ x,
    const float* __restrict__ Wq, const float* __restrict__ bq,
    float* __restrict__ out)
{
    const int warp = threadIdx.x >> 5;
    const int lane = threadIdx.x & 31;
    const int row  = (blockIdx.x * 4 + warp) * 2;

    // ---- Phase A: q gemv for two rows ----
    const float4* __restrict__ W0 = (const float4*)(Wq + (size_t)row * MSIZE);
    const float4* __restrict__ W1 = (const float4*)(Wq + (size_t)(row + 1) * MSIZE);
    const float4* __restrict__ xv = (const float4*)x;

    float acc0 = 0.0f, acc1 = 0.0f;
#pragma unroll 8
    for (int i = lane; i < MSIZE / 4; i += 32) {
        float4 w0 = __ldcs(W0 + i);
        float4 w1 = __ldcs(W1 + i);
        float4 xx = xv[i];
        acc0 = fmaf(w0.x, xx.x, acc0);
        acc0 = fmaf(w0.y, xx.y, acc0);
        acc0 = fmaf(w0.z, xx.z, acc0);
        acc0 = fmaf(w0.w, xx.w, acc0);
        acc1 = fmaf(w1.x, xx.x, acc1);
        acc1 = fmaf(w1.y, xx.y, acc1);
        acc1 = fmaf(w1.z, xx.z, acc1);
        acc1 = fmaf(w1.w, xx.w, acc1);
    }
#pragma unroll
    for (int off = 16; off > 0; off >>= 1) {
        acc0 += __shfl_xor_sync(0xffffffffu, acc0, off);
        acc1 += __shfl_xor_sync(0xffffffffu, acc1, off);
    }
    // xor-reduction leaves the full sum in every lane
    const float a0 = (acc0 + bq[row])     * A_SCALE;
    const float a1 = (acc1 + bq[row + 1]) * A_SCALE;

    // ---- Phase B: attention for the same two rows ----
    // No max-stabilization needed: |a*k| <= ~2 << fp32 exp range.
    const float4* __restrict__ kv = (const float4*)g_k;
    const float4* __restrict__ vv = (const float4*)g_v;

    float s0 = 0.0f, s1 = 0.0f, p0 = 0.0f, p1 = 0.0f;
#pragma unroll 4
    for (int i = lane; i < MSIZE / 4; i += 32) {
        float4 k4 = kv[i];
        float4 v4 = vv[i];

        float e;
        e = ex2f(a0 * k4.x); s0 += e; p0 = fmaf(e, v4.x, p0);
        e = ex2f(a0 * k4.y); s0 += e; p0 = fmaf(e, v4.y, p0);
        e = ex2f(a0 * k4.z); s0 += e; p0 = fmaf(e, v4.z, p0);
        e = ex2f(a0 * k4.w); s0 += e; p0 = fmaf(e, v4.w, p0);

        e = ex2f(a1 * k4.x); s1 += e; p1 = fmaf(e, v4.x, p1);
        e = ex2f(a1 * k4.y); s1 += e; p1 = fmaf(e, v4.y, p1);
        e = ex2f(a1 * k4.z); s1 += e; p1 = fmaf(e, v4.z, p1);
        e = ex2f(a1 * k4.w); s1 += e; p1 = fmaf(e, v4.w, p1);
    }

#pragma unroll
    for (int off = 16; off > 0; off >>= 1) {
        s0 += __shfl_xor_sync(0xffffffffu, s0, off);
        s1 += __shfl_xor_sync(0xffffffffu, s1, off);
        p0 += __shfl_xor_sync(0xffffffffu, p0, off);
        p1 += __shfl_xor_sync(0xffffffffu, p1, off);
    }

    if (lane == 0) {
        out[row]     = p0 / s0;
        out[row + 1] = p1 / s1;
    }
}

// ---------------------------------------------------------------------------
extern "C" void kernel_launch(void* const* d_in, const int* in_sizes, int n_in,
                              void* d_out, int out_size)
{
    const float* x  = (const float*)d_in[0];
    const float* Wq = (const float*)d_in[1];
    const float* bq = (const float*)d_in[2];
    const float* Wk = (const float*)d_in[3];
    const float* bk = (const float*)d_in[4];
    const float* Wv = (const float*)d_in[5];
    const float* bv = (const float*)d_in[6];
    float* out = (float*)d_out;

    kv_gemv<<<(2 * MSIZE / 2) / 8, 256>>>(x, Wk, bk, Wv, bv);
    q_attn<<<MSIZE / 8, 128>>>(x, Wq, bq, out);
}

// round 12
// speedup vs baseline: 1.0810x; 1.0810x over previous
#include <cuda_runtime.h>
#include <math.h>

#define MSIZE 8192
// a = q / sqrt(1024) ; fold log2(e) so exp(x) = ex2(x * log2e)
#define A_SCALE (1.44269504088896340736f / 32.0f)

// Scratch (no allocation allowed): q, k, v vectors
__device__ float g_q[MSIZE];
__device__ float g_k[MSIZE];
__device__ float g_v[MSIZE];

__device__ __forceinline__ float ex2f(float x) {
    float y;
    asm("ex2.approx.f32 %0, %1;" : "=f"(y) : "f"(x));
    return y;
}

// ---- packed f32x2 helpers (sm_103a) ----
__device__ __forceinline__ unsigned long long pk2(float lo, float hi) {
    unsigned long long r;
    asm("mov.b64 %0, {%1, %2};" : "=l"(r) : "f"(lo), "f"(hi));
    return r;
}
__device__ __forceinline__ void upk2(unsigned long long v, float& lo, float& hi) {
    asm("mov.b64 {%0, %1}, %2;" : "=f"(lo), "=f"(hi) : "l"(v));
}
__device__ __forceinline__ unsigned long long mul2(unsigned long long a, unsigned long long b) {
    unsigned long long r;
    asm("mul.rn.f32x2 %0, %1, %2;" : "=l"(r) : "l"(a), "l"(b));
    return r;
}
__device__ __forceinline__ unsigned long long add2(unsigned long long a, unsigned long long b) {
    unsigned long long r;
    asm("add.rn.f32x2 %0, %1, %2;" : "=l"(r) : "l"(a), "l"(b));
    return r;
}
__device__ __forceinline__ unsigned long long fma2(unsigned long long a, unsigned long long b,
                                                   unsigned long long c) {
    unsigned long long r;
    asm("fma.rn.f32x2 %0, %1, %2, %3;" : "=l"(r) : "l"(a), "l"(b), "l"(c));
    return r;
}

// ---------------------------------------------------------------------------
// Kernel 1: fused QKV GEMV (R5-proven config: 6.2 TB/s).
// One warp per TWO output rows; 8 warps per block; grid 1536; x in smem;
// W streamed with .cs; unroll 8.
// ---------------------------------------------------------------------------
__global__ __launch_bounds__(256) void qkv_gemv(
    const float* __restrict__ x,
    const float* __restrict__ Wq, const float* __restrict__ bq,
    const float* __restrict__ Wk, const float* __restrict__ bk,
    const float* __restrict__ Wv, const float* __restrict__ bv)
{
    __shared__ float sx[MSIZE];
    for (int i = threadIdx.x; i < MSIZE / 4; i += blockDim.x)
        ((float4*)sx)[i] = ((const float4*)x)[i];
    __syncthreads();

    const int warp = threadIdx.x >> 5;
    const int lane = threadIdx.x & 31;
    const int pair = blockIdx.x * 8 + warp;      // 0 .. 12287 (2 rows each)
    const int mat  = pair >> 12;                 // 4096 pairs per matrix
    const int row  = (pair & 4095) * 2;

    const float* W = (mat == 0) ? Wq : (mat == 1) ? Wk : Wv;
    const float* b = (mat == 0) ? bq : (mat == 1) ? bk : bv;
    float*       o = (mat == 0) ? g_q : (mat == 1) ? g_k : g_v;

    const float4* __restrict__ W0 = (const float4*)(W + (size_t)row * MSIZE);
    const float4* __restrict__ W1 = (const float4*)(W + (size_t)(row + 1) * MSIZE);
    const float4* __restrict__ xv = (const float4*)sx;

    float acc0 = 0.0f, acc1 = 0.0f;
#pragma unroll 8
    for (int i = lane; i < MSIZE / 4; i += 32) {
        float4 w0 = __ldcs(W0 + i);
        float4 w1 = __ldcs(W1 + i);
        float4 xx = xv[i];
        acc0 = fmaf(w0.x, xx.x, acc0);
        acc0 = fmaf(w0.y, xx.y, acc0);
        acc0 = fmaf(w0.z, xx.z, acc0);
        acc0 = fmaf(w0.w, xx.w, acc0);
        acc1 = fmaf(w1.x, xx.x, acc1);
        acc1 = fmaf(w1.y, xx.y, acc1);
        acc1 = fmaf(w1.z, xx.z, acc1);
        acc1 = fmaf(w1.w, xx.w, acc1);
    }
#pragma unroll
    for (int off = 16; off > 0; off >>= 1) {
        acc0 += __shfl_xor_sync(0xffffffffu, acc0, off);
        acc1 += __shfl_xor_sync(0xffffffffu, acc1, off);
    }

    if (lane == 0) {
        o[row]     = acc0 + b[row];
        o[row + 1] = acc1 + b[row + 1];
    }
}

// ---------------------------------------------------------------------------
// Kernel 2: rank-1 softmax attention with f32x2-packed math.
// Per row r and element pair (k0,k1): one mul.f32x2 (a*k0, a*k1), two ex2,
// one add.f32x2 (paired sum accum), one fma.f32x2 (paired weighted-v accum).
// Pairs come straight from float4 loads (consecutive regs -> movs elided).
// 2 rows/warp, 128 threads, grid 1024. k,v are L1-resident after warmup.
// ---------------------------------------------------------------------------
__global__ __launch_bounds__(128) void attn_rank1(float* __restrict__ out)
{
    const int warp = threadIdx.x >> 5;
    const int lane = threadIdx.x & 31;
    const int row0 = blockIdx.x * 8 + warp * 2;

    const float a0 = g_q[row0]     * A_SCALE;
    const float a1 = g_q[row0 + 1] * A_SCALE;
    const unsigned long long a00 = pk2(a0, a0);
    const unsigned long long a11 = pk2(a1, a1);

    const float4* __restrict__ kv = (const float4*)g_k;
    const float4* __restrict__ vv = (const float4*)g_v;

    unsigned long long s0p = 0ull, s1p = 0ull, p0p = 0ull, p1p = 0ull;  // (0.0f,0.0f) pairs

#pragma unroll 4
    for (int i = lane; i < MSIZE / 4; i += 32) {
        float4 k4 = kv[i];
        float4 v4 = vv[i];

        const unsigned long long kxy = pk2(k4.x, k4.y);
        const unsigned long long kzw = pk2(k4.z, k4.w);
        const unsigned long long vxy = pk2(v4.x, v4.y);
        const unsigned long long vzw = pk2(v4.z, v4.w);

        float lo, hi;

        // row 0, elements x,y
        upk2(mul2(a00, kxy), lo, hi);
        unsigned long long e = pk2(ex2f(lo), ex2f(hi));
        s0p = add2(s0p, e);
        p0p = fma2(e, vxy, p0p);
        // row 0, elements z,w
        upk2(mul2(a00, kzw), lo, hi);
        e = pk2(ex2f(lo), ex2f(hi));
        s0p = add2(s0p, e);
        p0p = fma2(e, vzw, p0p);

        // row 1, elements x,y
        upk2(mul2(a11, kxy), lo, hi);
        e = pk2(ex2f(lo), ex2f(hi));
        s1p = add2(s1p, e);
        p1p = fma2(e, vxy, p1p);
        // row 1, elements z,w
        upk2(mul2(a11, kzw), lo, hi);
        e = pk2(ex2f(lo), ex2f(hi));
        s1p = add2(s1p, e);
        p1p = fma2(e, vzw, p1p);
    }

    float lo, hi;
    upk2(s0p, lo, hi); float s0 = lo + hi;
    upk2(s1p, lo, hi); float s1 = lo + hi;
    upk2(p0p, lo, hi); float p0 = lo + hi;
    upk2(p1p, lo, hi); float p1 = lo + hi;

#pragma unroll
    for (int off = 16; off > 0; off >>= 1) {
        s0 += __shfl_xor_sync(0xffffffffu, s0, off);
        s1 += __shfl_xor_sync(0xffffffffu, s1, off);
        p0 += __shfl_xor_sync(0xffffffffu, p0, off);
        p1 += __shfl_xor_sync(0xffffffffu, p1, off);
    }

    if (lane == 0) {
        out[row0]     = p0 / s0;
        out[row0 + 1] = p1 / s1;
    }
}

// ---------------------------------------------------------------------------
extern "C" void kernel_launch(void* const* d_in, const int* in_sizes, int n_in,
                              void* d_out, int out_size)
{
    const float* x  = (const float*)d_in[0];
    const float* Wq = (const float*)d_in[1];
    const float* bq = (const float*)d_in[2];
    const float* Wk = (const float*)d_in[3];
    const float* bk = (const float*)d_in[4];
    const float* Wv = (const float*)d_in[5];
    const float* bv = (const float*)d_in[6];
    float* out = (float*)d_out;

    qkv_gemv<<<3 * (MSIZE / 2) / 8, 256>>>(x, Wq, bq, Wk, bk, Wv, bv);
    attn_rank1<<<MSIZE / 8, 128>>>(out);
}